// round 1
// baseline (speedup 1.0000x reference)
#include <cuda_runtime.h>
#include <math.h>

// ---------------- problem constants ----------------
#define B_  256
#define N_  4096
#define M_  64
#define C_  512
#define H_  4
#define IN_ 64
#define OUT_ 64
#define EPSF 1e-8f

static __device__ __constant__ int c_dummy = 0; // keep nvcc happy on empty constant use

static const size_t BN_ = (size_t)B_ * N_;

// ---------------- device scratch (no allocations allowed) ----------------
__device__ float g_mem[(size_t)B_ * N_ * M_];      // 256 MB working memory tensor
__device__ float g_wcat[2048 * 832];               // [W_ih | W_hh]
__device__ float g_bcat[2048];
__device__ float g_xcat[B_ * 832];                 // [in_data | prev_reads | h0]
__device__ float g_gates[B_ * 2048];
__device__ float g_c[B_ * C_];
__device__ float g_P[B_ * 560];                    // addressing params, 8 heads x 70
__device__ float g_EA[B_ * 512];                   // erase/add params, 4 heads x 128
__device__ float g_key[7 * B_ * 64];
__device__ float g_knorm[7 * B_];
__device__ float g_beta[7 * B_];
__device__ float g_gate[7 * B_];
__device__ float g_gamma[7 * B_];
__device__ float g_s[7 * B_ * 3];
__device__ float g_e[3 * B_ * 64];
__device__ float g_a[3 * B_ * 64];
__device__ float g_dot[7 * (size_t)B_ * N_];       // 28 MB
__device__ float g_nsq[(size_t)B_ * N_];           // 4 MB
__device__ float g_w[7 * (size_t)B_ * N_];         // 28 MB
__device__ float g_state[B_ * 768];                // [h | r0 | r1 | r2 | r3]
__device__ float g_outtmp[B_ * 64];

// ---------------- small math helpers ----------------
__device__ __forceinline__ float sigf(float x) { return 1.f / (1.f + expf(-x)); }
__device__ __forceinline__ float softplusf(float x) {
    return fmaxf(x, 0.f) + log1pf(expf(-fabsf(x)));
}
__device__ __forceinline__ float warpReduceSum(float v) {
    #pragma unroll
    for (int o = 16; o > 0; o >>= 1) v += __shfl_xor_sync(0xffffffffu, v, o);
    return v;
}
__device__ __forceinline__ float warpReduceMax(float v) {
    #pragma unroll
    for (int o = 16; o > 0; o >>= 1) v = fmaxf(v, __shfl_xor_sync(0xffffffffu, v, o));
    return v;
}
__device__ float blockReduceSum(float v, float* sh) {
    int lane = threadIdx.x & 31, wid = threadIdx.x >> 5;
    v = warpReduceSum(v);
    if (lane == 0) sh[wid] = v;
    __syncthreads();
    if (wid == 0) {
        float r = (lane < (int)(blockDim.x >> 5)) ? sh[lane] : 0.f;
        r = warpReduceSum(r);
        if (lane == 0) sh[0] = r;
    }
    __syncthreads();
    float r = sh[0];
    __syncthreads();
    return r;
}
__device__ float blockReduceMax(float v, float* sh) {
    int lane = threadIdx.x & 31, wid = threadIdx.x >> 5;
    v = warpReduceMax(v);
    if (lane == 0) sh[wid] = v;
    __syncthreads();
    if (wid == 0) {
        float r = (lane < (int)(blockDim.x >> 5)) ? sh[lane] : -INFINITY;
        r = warpReduceMax(r);
        if (lane == 0) sh[0] = r;
    }
    __syncthreads();
    float r = sh[0];
    __syncthreads();
    return r;
}

// ---------------- controller prep kernels ----------------
__global__ void k_build_wcat(const float* __restrict__ W_ih, const float* __restrict__ W_hh,
                             const float* __restrict__ b_ih, const float* __restrict__ b_hh) {
    int idx = blockIdx.x * blockDim.x + threadIdx.x;
    if (idx < 2048 * 832) {
        int j = idx / 832, k = idx % 832;
        g_wcat[idx] = (k < 320) ? W_ih[j * 320 + k] : W_hh[j * 512 + (k - 320)];
    }
    if (idx < 2048) g_bcat[idx] = b_ih[idx] + b_hh[idx];
}

__global__ void k_build_xcat(const float* __restrict__ in_data,
                             const float* __restrict__ prev_reads,
                             const float* __restrict__ h0) {
    int idx = blockIdx.x * blockDim.x + threadIdx.x;
    if (idx >= B_ * 832) return;
    int b = idx / 832, k = idx % 832;
    float v;
    if (k < 64) v = in_data[b * 64 + k];
    else if (k < 320) {
        int kk = k - 64;
        v = prev_reads[((kk / 64) * B_ + b) * 64 + (kk % 64)];
    } else v = h0[b * 512 + (k - 320)];
    g_xcat[idx] = v;
}

// Generic C = A @ B^T + bias.  A:[MM,K] row-major, B:[NN,K] row-major, C:[MM,NN].
// MM multiple of 64, K multiple of 16.
__global__ void k_sgemm(const float* __restrict__ A, const float* __restrict__ Bm,
                        const float* __restrict__ bias, float* __restrict__ Cm,
                        int MMr, int NNc, int K) {
    __shared__ float As[16][64];
    __shared__ float Bs[16][64];
    int tid = threadIdx.x;
    int tx = tid & 15, ty = tid >> 4;
    int bx = blockIdx.x, by = blockIdx.y;
    float acc[4][4] = {};
    int lr = tid >> 2;
    int kq = (tid & 3) * 4;
    int arow = by * 64 + lr;
    int brow = bx * 64 + lr;
    for (int k0 = 0; k0 < K; k0 += 16) {
        float4 av = *(const float4*)&A[(size_t)arow * K + k0 + kq];
        float4 bv = make_float4(0.f, 0.f, 0.f, 0.f);
        if (brow < NNc) bv = *(const float4*)&Bm[(size_t)brow * K + k0 + kq];
        As[kq + 0][lr] = av.x; As[kq + 1][lr] = av.y; As[kq + 2][lr] = av.z; As[kq + 3][lr] = av.w;
        Bs[kq + 0][lr] = bv.x; Bs[kq + 1][lr] = bv.y; Bs[kq + 2][lr] = bv.z; Bs[kq + 3][lr] = bv.w;
        __syncthreads();
        #pragma unroll
        for (int kk = 0; kk < 16; kk++) {
            float4 a4 = *(float4*)&As[kk][ty * 4];
            float4 b4 = *(float4*)&Bs[kk][tx * 4];
            float a[4] = {a4.x, a4.y, a4.z, a4.w};
            float bb[4] = {b4.x, b4.y, b4.z, b4.w};
            #pragma unroll
            for (int i = 0; i < 4; i++)
                #pragma unroll
                for (int j = 0; j < 4; j++)
                    acc[i][j] = fmaf(a[i], bb[j], acc[i][j]);
        }
        __syncthreads();
    }
    #pragma unroll
    for (int i = 0; i < 4; i++) {
        int row = by * 64 + ty * 4 + i;
        #pragma unroll
        for (int j = 0; j < 4; j++) {
            int col = bx * 64 + tx * 4 + j;
            if (col < NNc) Cm[(size_t)row * NNc + col] = acc[i][j] + bias[col];
        }
    }
}

__global__ void k_lstm(const float* __restrict__ c0) {
    int idx = blockIdx.x * blockDim.x + threadIdx.x;
    if (idx >= B_ * C_) return;
    int b = idx >> 9, j = idx & 511;
    const float* g = g_gates + (size_t)b * 2048;
    float ig = sigf(g[j]);
    float fg = sigf(g[512 + j]);
    float gg = tanhf(g[1024 + j]);
    float og = sigf(g[1536 + j]);
    float cn = fg * c0[idx] + ig * gg;
    g_c[idx] = cn;
    g_state[(size_t)b * 768 + j] = og * tanhf(cn);
}

__global__ void k_zero_reads() {
    int idx = blockIdx.x * blockDim.x + threadIdx.x;
    if (idx >= B_ * 256) return;
    g_state[(idx >> 8) * 768 + 512 + (idx & 255)] = 0.f;
}

// per-head param transforms (keys, beta, gate, shift softmax, gamma, e/a)
__global__ void k_params() {
    int b = blockIdx.x;
    int tid = threadIdx.x; // 64 threads
    __shared__ float sh[64];
    for (int hi = 0; hi < 7; ++hi) {
        float kv = 0.f;
        {
            float p = g_P[b * 560 + hi * 70 + tid];
            kv = tanhf(p);
            g_key[(hi * B_ + b) * 64 + tid] = kv;
            sh[tid] = kv * kv;
        }
        __syncthreads();
        if (tid == 0) {
            float s = 0.f;
            for (int m = 0; m < 64; m++) s += sh[m];
            g_knorm[hi * B_ + b] = sqrtf(s);
            const float* pp = &g_P[b * 560 + hi * 70];
            g_beta[hi * B_ + b] = softplusf(pp[64]);
            g_gate[hi * B_ + b] = sigf(pp[65]);
            float s0 = pp[66], s1 = pp[67], s2 = pp[68];
            float mx = fmaxf(s0, fmaxf(s1, s2));
            float e0 = expf(s0 - mx), e1 = expf(s1 - mx), e2 = expf(s2 - mx);
            float ss = e0 + e1 + e2;
            g_s[(hi * B_ + b) * 3 + 0] = e0 / ss;
            g_s[(hi * B_ + b) * 3 + 1] = e1 / ss;
            g_s[(hi * B_ + b) * 3 + 2] = e2 / ss;
            g_gamma[hi * B_ + b] = 1.f + softplusf(pp[69]);
        }
        __syncthreads();
    }
    for (int wh = 0; wh < 3; ++wh) {
        g_e[(wh * B_ + b) * 64 + tid] = sigf(g_EA[b * 512 + wh * 128 + tid]);
        g_a[(wh * B_ + b) * 64 + tid] = tanhf(g_EA[b * 512 + wh * 128 + 64 + tid]);
    }
}

// ---------------- addressing weight kernel (one block per (b, head)) ----------------
__global__ void k_weight(const float* __restrict__ prev_weights, int head_base) {
    const int b = blockIdx.x;
    const int hi = head_base + blockIdx.y;
    const int tid = threadIdx.x; // 512
    __shared__ float swg[N_];
    __shared__ float sred[16];
    const size_t base = (size_t)hi * B_ + b;
    const float beta = g_beta[base], knorm = g_knorm[base], gate = g_gate[base], gamma = g_gamma[base];
    const float s0 = g_s[base * 3], s1 = g_s[base * 3 + 1], s2 = g_s[base * 3 + 2];
    const float* dot = g_dot + (size_t)hi * BN_ + (size_t)b * N_;
    const float* nsq = g_nsq + (size_t)b * N_;
    const float* pw = prev_weights + base * N_;
    float* wout = g_w + (size_t)hi * BN_ + (size_t)b * N_;

    float sim[8];
    float lmax = -INFINITY;
    #pragma unroll
    for (int i = 0; i < 8; i++) {
        int n = tid + i * 512;
        float denom = sqrtf(nsq[n]) * knorm + EPSF;
        sim[i] = beta * dot[n] / denom;
        lmax = fmaxf(lmax, sim[i]);
    }
    float mx = blockReduceMax(lmax, sred);
    float lsum = 0.f;
    #pragma unroll
    for (int i = 0; i < 8; i++) { sim[i] = expf(sim[i] - mx); lsum += sim[i]; }
    float Z = blockReduceSum(lsum, sred);
    float invZ = 1.f / Z;
    #pragma unroll
    for (int i = 0; i < 8; i++) {
        int n = tid + i * 512;
        swg[n] = gate * sim[i] * invZ + (1.f - gate) * pw[n];
    }
    __syncthreads();
    float wp[8];
    lsum = 0.f;
    #pragma unroll
    for (int i = 0; i < 8; i++) {
        int n = tid + i * 512;
        float ws = s0 * swg[(n + N_ - 1) & (N_ - 1)] + s1 * swg[n] + s2 * swg[(n + 1) & (N_ - 1)];
        wp[i] = powf(ws, gamma);
        lsum += wp[i];
    }
    float S = blockReduceSum(lsum, sred);
    float inv = 1.f / (S + EPSF);
    #pragma unroll
    for (int i = 0; i < 8; i++) wout[tid + i * 512] = wp[i] * inv;
}

// ---------------- fused memory pass ----------------
// Per (b,n) row: optional read-head accumulate (old row), optional write-head
// update (-> g_mem), and dot products of the *resulting* row with next heads'
// keys plus its squared norm.
#define PASS_ROWS 128
#define PASS_ITER 8

template <bool HR, bool HW, int ND>
__global__ void k_pass(const float* __restrict__ src, int rhead, int rslot,
                       int whead, int whidx, int d0, int d1) {
    const int b = blockIdx.y;
    __shared__ float4 sk0[16], sk1[16], se[16], sa[16];
    __shared__ float sred[8][64];
    const int tid = threadIdx.x;
    if (ND >= 1 && tid < 16)
        sk0[tid] = ((const float4*)(g_key + ((size_t)d0 * B_ + b) * 64))[tid];
    if (ND >= 2 && tid >= 16 && tid < 32)
        sk1[tid - 16] = ((const float4*)(g_key + ((size_t)d1 * B_ + b) * 64))[tid - 16];
    if (HW && tid >= 32 && tid < 48)
        se[tid - 32] = ((const float4*)(g_e + ((size_t)whidx * B_ + b) * 64))[tid - 32];
    if (HW && tid >= 48 && tid < 64)
        sa[tid - 48] = ((const float4*)(g_a + ((size_t)whidx * B_ + b) * 64))[tid - 48];
    __syncthreads();

    const int lane = tid & 31, warp = tid >> 5, sub = lane & 15, half = lane >> 4;
    float4 racc = make_float4(0.f, 0.f, 0.f, 0.f);
    const float* wr_p = g_w + ((size_t)rhead * B_ + b) * N_;
    const float* ww_p = g_w + ((size_t)whead * B_ + b) * N_;
    const size_t rowbase = (size_t)b * N_ * 64;
    const int n0 = blockIdx.x * PASS_ROWS + warp * 2 + half;

    #pragma unroll
    for (int it = 0; it < PASS_ITER; ++it) {
        const int n = n0 + it * 16;
        float4 v = ((const float4*)(src + rowbase + (size_t)n * 64))[sub];
        if (HR) {
            float wr = wr_p[n];
            racc.x = fmaf(wr, v.x, racc.x);
            racc.y = fmaf(wr, v.y, racc.y);
            racc.z = fmaf(wr, v.z, racc.z);
            racc.w = fmaf(wr, v.w, racc.w);
        }
        if (HW) {
            float ww = ww_p[n];
            float4 e4 = se[sub], a4 = sa[sub];
            v.x = v.x * (1.f - ww * e4.x) + ww * a4.x;
            v.y = v.y * (1.f - ww * e4.y) + ww * a4.y;
            v.z = v.z * (1.f - ww * e4.z) + ww * a4.z;
            v.w = v.w * (1.f - ww * e4.w) + ww * a4.w;
            ((float4*)(g_mem + rowbase + (size_t)n * 64))[sub] = v;
        }
        if (ND >= 1) {
            float4 k0v = sk0[sub];
            float dv0 = v.x * k0v.x + v.y * k0v.y + v.z * k0v.z + v.w * k0v.w;
            float nv = v.x * v.x + v.y * v.y + v.z * v.z + v.w * v.w;
            float dv1 = 0.f;
            if (ND >= 2) {
                float4 k1v = sk1[sub];
                dv1 = v.x * k1v.x + v.y * k1v.y + v.z * k1v.z + v.w * k1v.w;
            }
            #pragma unroll
            for (int m = 8; m >= 1; m >>= 1) {
                dv0 += __shfl_xor_sync(0xffffffffu, dv0, m);
                nv += __shfl_xor_sync(0xffffffffu, nv, m);
                if (ND >= 2) dv1 += __shfl_xor_sync(0xffffffffu, dv1, m);
            }
            if (sub == 0) {
                g_dot[(size_t)d0 * BN_ + (size_t)b * N_ + n] = dv0;
                if (ND >= 2) g_dot[(size_t)d1 * BN_ + (size_t)b * N_ + n] = dv1;
                g_nsq[(size_t)b * N_ + n] = nv;
            }
        }
    }

    if (HR) {
        racc.x += __shfl_xor_sync(0xffffffffu, racc.x, 16);
        racc.y += __shfl_xor_sync(0xffffffffu, racc.y, 16);
        racc.z += __shfl_xor_sync(0xffffffffu, racc.z, 16);
        racc.w += __shfl_xor_sync(0xffffffffu, racc.w, 16);
        if (half == 0) {
            sred[warp][sub * 4 + 0] = racc.x;
            sred[warp][sub * 4 + 1] = racc.y;
            sred[warp][sub * 4 + 2] = racc.z;
            sred[warp][sub * 4 + 3] = racc.w;
        }
        __syncthreads();
        if (tid < 64) {
            float s = 0.f;
            #pragma unroll
            for (int w2 = 0; w2 < 8; ++w2) s += sred[w2][tid];
            atomicAdd(&g_state[(size_t)b * 768 + 512 + rslot * 64 + tid], s);
        }
    }
}

__global__ void k_sig_out(float* __restrict__ out) {
    int idx = blockIdx.x * blockDim.x + threadIdx.x;
    if (idx >= B_ * 64) return;
    out[idx] = sigf(g_outtmp[idx]);
}

// ---------------- launch ----------------
extern "C" void kernel_launch(void* const* d_in, const int* in_sizes, int n_in,
                              void* d_out, int out_size) {
    const float* in_data = (const float*)d_in[0];
    const float* memory = (const float*)d_in[1];
    const float* h0 = (const float*)d_in[2];
    const float* c0 = (const float*)d_in[3];
    const float* prev_weights = (const float*)d_in[4];
    const float* prev_reads = (const float*)d_in[5];
    const float* W_ih = (const float*)d_in[6];
    const float* b_ih = (const float*)d_in[7];
    const float* W_hh = (const float*)d_in[8];
    const float* b_hh = (const float*)d_in[9];
    const float* W_out = (const float*)d_in[10];
    const float* b_out = (const float*)d_in[11];
    const float* W_addr = (const float*)d_in[12];
    const float* b_addr = (const float*)d_in[13];
    const float* W_ea = (const float*)d_in[14];
    const float* b_ea = (const float*)d_in[15];
    float* out = (float*)d_out;
    (void)in_sizes; (void)n_in; (void)out_size;

    float *p_xcat, *p_wcat, *p_bcat, *p_gates, *p_c, *p_P, *p_EA, *p_state, *p_outtmp, *p_mem;
    cudaGetSymbolAddress((void**)&p_xcat, g_xcat);
    cudaGetSymbolAddress((void**)&p_wcat, g_wcat);
    cudaGetSymbolAddress((void**)&p_bcat, g_bcat);
    cudaGetSymbolAddress((void**)&p_gates, g_gates);
    cudaGetSymbolAddress((void**)&p_c, g_c);
    cudaGetSymbolAddress((void**)&p_P, g_P);
    cudaGetSymbolAddress((void**)&p_EA, g_EA);
    cudaGetSymbolAddress((void**)&p_state, g_state);
    cudaGetSymbolAddress((void**)&p_outtmp, g_outtmp);
    cudaGetSymbolAddress((void**)&p_mem, g_mem);

    // controller
    k_build_wcat<<<(2048 * 832 + 255) / 256, 256>>>(W_ih, W_hh, b_ih, b_hh);
    k_build_xcat<<<(B_ * 832 + 255) / 256, 256>>>(in_data, prev_reads, h0);
    k_sgemm<<<dim3(32, 4), 256>>>(p_xcat, p_wcat, p_bcat, p_gates, 256, 2048, 832);
    k_lstm<<<(B_ * C_ + 255) / 256, 256>>>(c0);
    k_zero_reads<<<(B_ * 256 + 255) / 256, 256>>>();

    // per-head parameters (head 7 is dead: its write is never observed)
    k_sgemm<<<dim3(9, 4), 256>>>(p_c, W_addr, b_addr, p_P, 256, 560, 512);
    k_sgemm<<<dim3(8, 4), 256>>>(p_c, W_ea, b_ea, p_EA, 256, 512, 512);
    k_params<<<256, 64>>>();

    // pass 0: dots for heads 0,1 + norms over mem0 (input)
    k_pass<false, false, 2><<<dim3(N_ / PASS_ROWS, B_), 256>>>(memory, 0, 0, 0, 0, 0, 1);
    k_weight<<<dim3(B_, 2), 512>>>(prev_weights, 0);
    // pass 1: read h0 (mem0), write h1 -> mem1, dots for heads 2,3 + norms(mem1)
    k_pass<true, true, 2><<<dim3(N_ / PASS_ROWS, B_), 256>>>(memory, 0, 0, 1, 0, 2, 3);
    k_weight<<<dim3(B_, 2), 512>>>(prev_weights, 2);
    // pass 2: read h2 (mem1), write h3 -> mem2, dots for heads 4,5
    k_pass<true, true, 2><<<dim3(N_ / PASS_ROWS, B_), 256>>>(p_mem, 2, 1, 3, 1, 4, 5);
    k_weight<<<dim3(B_, 2), 512>>>(prev_weights, 4);
    // pass 3: read h4 (mem2), write h5 -> mem3, dot for head 6
    k_pass<true, true, 1><<<dim3(N_ / PASS_ROWS, B_), 256>>>(p_mem, 4, 2, 5, 2, 6, 0);
    k_weight<<<dim3(B_, 1), 512>>>(prev_weights, 6);
    // pass 4: read h6 (mem3) only — head 7's write is dead
    k_pass<true, false, 0><<<dim3(N_ / PASS_ROWS, B_), 256>>>(p_mem, 6, 3, 0, 0, 0, 0);

    // output layer
    k_sgemm<<<dim3(1, 4), 256>>>(p_state, W_out, b_out, p_outtmp, 256, 64, 768);
    k_sig_out<<<(B_ * 64 + 255) / 256, 256>>>(out);
}

// round 2
// speedup vs baseline: 1.0008x; 1.0008x over previous
#include <cuda_runtime.h>
#include <math.h>

// ---------------- problem constants ----------------
#define B_  256
#define N_  4096
#define M_  64
#define C_  512
#define H_  4
#define IN_ 64
#define OUT_ 64
#define EPSF 1e-8f

static __device__ __constant__ int c_dummy = 0; // keep nvcc happy on empty constant use

static const size_t BN_ = (size_t)B_ * N_;

// ---------------- device scratch (no allocations allowed) ----------------
__device__ float g_mem[(size_t)B_ * N_ * M_];      // 256 MB working memory tensor
__device__ float g_wcat[2048 * 832];               // [W_ih | W_hh]
__device__ float g_bcat[2048];
__device__ float g_xcat[B_ * 832];                 // [in_data | prev_reads | h0]
__device__ float g_gates[B_ * 2048];
__device__ float g_c[B_ * C_];
__device__ float g_P[B_ * 560];                    // addressing params, 8 heads x 70
__device__ float g_EA[B_ * 512];                   // erase/add params, 4 heads x 128
__device__ float g_key[7 * B_ * 64];
__device__ float g_knorm[7 * B_];
__device__ float g_beta[7 * B_];
__device__ float g_gate[7 * B_];
__device__ float g_gamma[7 * B_];
__device__ float g_s[7 * B_ * 3];
__device__ float g_e[3 * B_ * 64];
__device__ float g_a[3 * B_ * 64];
__device__ float g_dot[7 * (size_t)B_ * N_];       // 28 MB
__device__ float g_nsq[(size_t)B_ * N_];           // 4 MB
__device__ float g_w[7 * (size_t)B_ * N_];         // 28 MB
__device__ float g_state[B_ * 768];                // [h | r0 | r1 | r2 | r3]
__device__ float g_outtmp[B_ * 64];

// ---------------- small math helpers ----------------
__device__ __forceinline__ float sigf(float x) { return 1.f / (1.f + expf(-x)); }
__device__ __forceinline__ float softplusf(float x) {
    return fmaxf(x, 0.f) + log1pf(expf(-fabsf(x)));
}
__device__ __forceinline__ float warpReduceSum(float v) {
    #pragma unroll
    for (int o = 16; o > 0; o >>= 1) v += __shfl_xor_sync(0xffffffffu, v, o);
    return v;
}
__device__ __forceinline__ float warpReduceMax(float v) {
    #pragma unroll
    for (int o = 16; o > 0; o >>= 1) v = fmaxf(v, __shfl_xor_sync(0xffffffffu, v, o));
    return v;
}
__device__ float blockReduceSum(float v, float* sh) {
    int lane = threadIdx.x & 31, wid = threadIdx.x >> 5;
    v = warpReduceSum(v);
    if (lane == 0) sh[wid] = v;
    __syncthreads();
    if (wid == 0) {
        float r = (lane < (int)(blockDim.x >> 5)) ? sh[lane] : 0.f;
        r = warpReduceSum(r);
        if (lane == 0) sh[0] = r;
    }
    __syncthreads();
    float r = sh[0];
    __syncthreads();
    return r;
}
__device__ float blockReduceMax(float v, float* sh) {
    int lane = threadIdx.x & 31, wid = threadIdx.x >> 5;
    v = warpReduceMax(v);
    if (lane == 0) sh[wid] = v;
    __syncthreads();
    if (wid == 0) {
        float r = (lane < (int)(blockDim.x >> 5)) ? sh[lane] : -INFINITY;
        r = warpReduceMax(r);
        if (lane == 0) sh[0] = r;
    }
    __syncthreads();
    float r = sh[0];
    __syncthreads();
    return r;
}

// ---------------- controller prep kernels ----------------
__global__ void k_build_wcat(const float* __restrict__ W_ih, const float* __restrict__ W_hh,
                             const float* __restrict__ b_ih, const float* __restrict__ b_hh) {
    int idx = blockIdx.x * blockDim.x + threadIdx.x;
    if (idx < 2048 * 832) {
        int j = idx / 832, k = idx % 832;
        g_wcat[idx] = (k < 320) ? W_ih[j * 320 + k] : W_hh[j * 512 + (k - 320)];
    }
    if (idx < 2048) g_bcat[idx] = b_ih[idx] + b_hh[idx];
}

__global__ void k_build_xcat(const float* __restrict__ in_data,
                             const float* __restrict__ prev_reads,
                             const float* __restrict__ h0) {
    int idx = blockIdx.x * blockDim.x + threadIdx.x;
    if (idx >= B_ * 832) return;
    int b = idx / 832, k = idx % 832;
    float v;
    if (k < 64) v = in_data[b * 64 + k];
    else if (k < 320) {
        int kk = k - 64;
        v = prev_reads[((kk / 64) * B_ + b) * 64 + (kk % 64)];
    } else v = h0[b * 512 + (k - 320)];
    g_xcat[idx] = v;
}

// Generic C = A @ B^T + bias.  A:[MM,K] row-major, B:[NN,K] row-major, C:[MM,NN].
// MM multiple of 64, K multiple of 16.
__global__ void k_sgemm(const float* __restrict__ A, const float* __restrict__ Bm,
                        const float* __restrict__ bias, float* __restrict__ Cm,
                        int MMr, int NNc, int K) {
    __shared__ float As[16][64];
    __shared__ float Bs[16][64];
    int tid = threadIdx.x;
    int tx = tid & 15, ty = tid >> 4;
    int bx = blockIdx.x, by = blockIdx.y;
    float acc[4][4] = {};
    int lr = tid >> 2;
    int kq = (tid & 3) * 4;
    int arow = by * 64 + lr;
    int brow = bx * 64 + lr;
    for (int k0 = 0; k0 < K; k0 += 16) {
        float4 av = *(const float4*)&A[(size_t)arow * K + k0 + kq];
        float4 bv = make_float4(0.f, 0.f, 0.f, 0.f);
        if (brow < NNc) bv = *(const float4*)&Bm[(size_t)brow * K + k0 + kq];
        As[kq + 0][lr] = av.x; As[kq + 1][lr] = av.y; As[kq + 2][lr] = av.z; As[kq + 3][lr] = av.w;
        Bs[kq + 0][lr] = bv.x; Bs[kq + 1][lr] = bv.y; Bs[kq + 2][lr] = bv.z; Bs[kq + 3][lr] = bv.w;
        __syncthreads();
        #pragma unroll
        for (int kk = 0; kk < 16; kk++) {
            float4 a4 = *(float4*)&As[kk][ty * 4];
            float4 b4 = *(float4*)&Bs[kk][tx * 4];
            float a[4] = {a4.x, a4.y, a4.z, a4.w};
            float bb[4] = {b4.x, b4.y, b4.z, b4.w};
            #pragma unroll
            for (int i = 0; i < 4; i++)
                #pragma unroll
                for (int j = 0; j < 4; j++)
                    acc[i][j] = fmaf(a[i], bb[j], acc[i][j]);
        }
        __syncthreads();
    }
    #pragma unroll
    for (int i = 0; i < 4; i++) {
        int row = by * 64 + ty * 4 + i;
        #pragma unroll
        for (int j = 0; j < 4; j++) {
            int col = bx * 64 + tx * 4 + j;
            if (col < NNc) Cm[(size_t)row * NNc + col] = acc[i][j] + bias[col];
        }
    }
}

__global__ void k_lstm(const float* __restrict__ c0) {
    int idx = blockIdx.x * blockDim.x + threadIdx.x;
    if (idx >= B_ * C_) return;
    int b = idx >> 9, j = idx & 511;
    const float* g = g_gates + (size_t)b * 2048;
    float ig = sigf(g[j]);
    float fg = sigf(g[512 + j]);
    float gg = tanhf(g[1024 + j]);
    float og = sigf(g[1536 + j]);
    float cn = fg * c0[idx] + ig * gg;
    g_c[idx] = cn;
    g_state[(size_t)b * 768 + j] = og * tanhf(cn);
}

__global__ void k_zero_reads() {
    int idx = blockIdx.x * blockDim.x + threadIdx.x;
    if (idx >= B_ * 256) return;
    g_state[(idx >> 8) * 768 + 512 + (idx & 255)] = 0.f;
}

// per-head param transforms (keys, beta, gate, shift softmax, gamma, e/a)
__global__ void k_params() {
    int b = blockIdx.x;
    int tid = threadIdx.x; // 64 threads
    __shared__ float sh[64];
    for (int hi = 0; hi < 7; ++hi) {
        float kv = 0.f;
        {
            float p = g_P[b * 560 + hi * 70 + tid];
            kv = tanhf(p);
            g_key[(hi * B_ + b) * 64 + tid] = kv;
            sh[tid] = kv * kv;
        }
        __syncthreads();
        if (tid == 0) {
            float s = 0.f;
            for (int m = 0; m < 64; m++) s += sh[m];
            g_knorm[hi * B_ + b] = sqrtf(s);
            const float* pp = &g_P[b * 560 + hi * 70];
            g_beta[hi * B_ + b] = softplusf(pp[64]);
            g_gate[hi * B_ + b] = sigf(pp[65]);
            float s0 = pp[66], s1 = pp[67], s2 = pp[68];
            float mx = fmaxf(s0, fmaxf(s1, s2));
            float e0 = expf(s0 - mx), e1 = expf(s1 - mx), e2 = expf(s2 - mx);
            float ss = e0 + e1 + e2;
            g_s[(hi * B_ + b) * 3 + 0] = e0 / ss;
            g_s[(hi * B_ + b) * 3 + 1] = e1 / ss;
            g_s[(hi * B_ + b) * 3 + 2] = e2 / ss;
            g_gamma[hi * B_ + b] = 1.f + softplusf(pp[69]);
        }
        __syncthreads();
    }
    for (int wh = 0; wh < 3; ++wh) {
        g_e[(wh * B_ + b) * 64 + tid] = sigf(g_EA[b * 512 + wh * 128 + tid]);
        g_a[(wh * B_ + b) * 64 + tid] = tanhf(g_EA[b * 512 + wh * 128 + 64 + tid]);
    }
}

// ---------------- addressing weight kernel (one block per (b, head)) ----------------
__global__ void k_weight(const float* __restrict__ prev_weights, int head_base) {
    const int b = blockIdx.x;
    const int hi = head_base + blockIdx.y;
    const int tid = threadIdx.x; // 512
    __shared__ float swg[N_];
    __shared__ float sred[16];
    const size_t base = (size_t)hi * B_ + b;
    const float beta = g_beta[base], knorm = g_knorm[base], gate = g_gate[base], gamma = g_gamma[base];
    const float s0 = g_s[base * 3], s1 = g_s[base * 3 + 1], s2 = g_s[base * 3 + 2];
    const float* dot = g_dot + (size_t)hi * BN_ + (size_t)b * N_;
    const float* nsq = g_nsq + (size_t)b * N_;
    const float* pw = prev_weights + base * N_;
    float* wout = g_w + (size_t)hi * BN_ + (size_t)b * N_;

    float sim[8];
    float lmax = -INFINITY;
    #pragma unroll
    for (int i = 0; i < 8; i++) {
        int n = tid + i * 512;
        float denom = sqrtf(nsq[n]) * knorm + EPSF;
        sim[i] = beta * dot[n] / denom;
        lmax = fmaxf(lmax, sim[i]);
    }
    float mx = blockReduceMax(lmax, sred);
    float lsum = 0.f;
    #pragma unroll
    for (int i = 0; i < 8; i++) { sim[i] = expf(sim[i] - mx); lsum += sim[i]; }
    float Z = blockReduceSum(lsum, sred);
    float invZ = 1.f / Z;
    #pragma unroll
    for (int i = 0; i < 8; i++) {
        int n = tid + i * 512;
        swg[n] = gate * sim[i] * invZ + (1.f - gate) * pw[n];
    }
    __syncthreads();
    float wp[8];
    lsum = 0.f;
    #pragma unroll
    for (int i = 0; i < 8; i++) {
        int n = tid + i * 512;
        float ws = s0 * swg[(n + N_ - 1) & (N_ - 1)] + s1 * swg[n] + s2 * swg[(n + 1) & (N_ - 1)];
        wp[i] = powf(ws, gamma);
        lsum += wp[i];
    }
    float S = blockReduceSum(lsum, sred);
    float inv = 1.f / (S + EPSF);
    #pragma unroll
    for (int i = 0; i < 8; i++) wout[tid + i * 512] = wp[i] * inv;
}

// ---------------- fused memory pass ----------------
// Per (b,n) row: optional read-head accumulate (old row), optional write-head
// update (-> g_mem), and dot products of the *resulting* row with next heads'
// keys plus its squared norm.
#define PASS_ROWS 128
#define PASS_ITER 8

template <bool HR, bool HW, int ND>
__global__ void k_pass(const float* __restrict__ src, int rhead, int rslot,
                       int whead, int whidx, int d0, int d1) {
    const int b = blockIdx.y;
    __shared__ float4 sk0[16], sk1[16], se[16], sa[16];
    __shared__ float sred[8][64];
    const int tid = threadIdx.x;
    if (ND >= 1 && tid < 16)
        sk0[tid] = ((const float4*)(g_key + ((size_t)d0 * B_ + b) * 64))[tid];
    if (ND >= 2 && tid >= 16 && tid < 32)
        sk1[tid - 16] = ((const float4*)(g_key + ((size_t)d1 * B_ + b) * 64))[tid - 16];
    if (HW && tid >= 32 && tid < 48)
        se[tid - 32] = ((const float4*)(g_e + ((size_t)whidx * B_ + b) * 64))[tid - 32];
    if (HW && tid >= 48 && tid < 64)
        sa[tid - 48] = ((const float4*)(g_a + ((size_t)whidx * B_ + b) * 64))[tid - 48];
    __syncthreads();

    const int lane = tid & 31, warp = tid >> 5, sub = lane & 15, half = lane >> 4;
    float4 racc = make_float4(0.f, 0.f, 0.f, 0.f);
    const float* wr_p = g_w + ((size_t)rhead * B_ + b) * N_;
    const float* ww_p = g_w + ((size_t)whead * B_ + b) * N_;
    const size_t rowbase = (size_t)b * N_ * 64;
    const int n0 = blockIdx.x * PASS_ROWS + warp * 2 + half;

    #pragma unroll
    for (int it = 0; it < PASS_ITER; ++it) {
        const int n = n0 + it * 16;
        float4 v = ((const float4*)(src + rowbase + (size_t)n * 64))[sub];
        if (HR) {
            float wr = wr_p[n];
            racc.x = fmaf(wr, v.x, racc.x);
            racc.y = fmaf(wr, v.y, racc.y);
            racc.z = fmaf(wr, v.z, racc.z);
            racc.w = fmaf(wr, v.w, racc.w);
        }
        if (HW) {
            float ww = ww_p[n];
            float4 e4 = se[sub], a4 = sa[sub];
            v.x = v.x * (1.f - ww * e4.x) + ww * a4.x;
            v.y = v.y * (1.f - ww * e4.y) + ww * a4.y;
            v.z = v.z * (1.f - ww * e4.z) + ww * a4.z;
            v.w = v.w * (1.f - ww * e4.w) + ww * a4.w;
            ((float4*)(g_mem + rowbase + (size_t)n * 64))[sub] = v;
        }
        if (ND >= 1) {
            float4 k0v = sk0[sub];
            float dv0 = v.x * k0v.x + v.y * k0v.y + v.z * k0v.z + v.w * k0v.w;
            float nv = v.x * v.x + v.y * v.y + v.z * v.z + v.w * v.w;
            float dv1 = 0.f;
            if (ND >= 2) {
                float4 k1v = sk1[sub];
                dv1 = v.x * k1v.x + v.y * k1v.y + v.z * k1v.z + v.w * k1v.w;
            }
            #pragma unroll
            for (int m = 8; m >= 1; m >>= 1) {
                dv0 += __shfl_xor_sync(0xffffffffu, dv0, m);
                nv += __shfl_xor_sync(0xffffffffu, nv, m);
                if (ND >= 2) dv1 += __shfl_xor_sync(0xffffffffu, dv1, m);
            }
            if (sub == 0) {
                g_dot[(size_t)d0 * BN_ + (size_t)b * N_ + n] = dv0;
                if (ND >= 2) g_dot[(size_t)d1 * BN_ + (size_t)b * N_ + n] = dv1;
                g_nsq[(size_t)b * N_ + n] = nv;
            }
        }
    }

    if (HR) {
        racc.x += __shfl_xor_sync(0xffffffffu, racc.x, 16);
        racc.y += __shfl_xor_sync(0xffffffffu, racc.y, 16);
        racc.z += __shfl_xor_sync(0xffffffffu, racc.z, 16);
        racc.w += __shfl_xor_sync(0xffffffffu, racc.w, 16);
        if (half == 0) {
            sred[warp][sub * 4 + 0] = racc.x;
            sred[warp][sub * 4 + 1] = racc.y;
            sred[warp][sub * 4 + 2] = racc.z;
            sred[warp][sub * 4 + 3] = racc.w;
        }
        __syncthreads();
        if (tid < 64) {
            float s = 0.f;
            #pragma unroll
            for (int w2 = 0; w2 < 8; ++w2) s += sred[w2][tid];
            atomicAdd(&g_state[(size_t)b * 768 + 512 + rslot * 64 + tid], s);
        }
    }
}

__global__ void k_sig_out(float* __restrict__ out) {
    int idx = blockIdx.x * blockDim.x + threadIdx.x;
    if (idx >= B_ * 64) return;
    out[idx] = sigf(g_outtmp[idx]);
}

// ---------------- launch ----------------
extern "C" void kernel_launch(void* const* d_in, const int* in_sizes, int n_in,
                              void* d_out, int out_size) {
    const float* in_data = (const float*)d_in[0];
    const float* memory = (const float*)d_in[1];
    const float* h0 = (const float*)d_in[2];
    const float* c0 = (const float*)d_in[3];
    const float* prev_weights = (const float*)d_in[4];
    const float* prev_reads = (const float*)d_in[5];
    const float* W_ih = (const float*)d_in[6];
    const float* b_ih = (const float*)d_in[7];
    const float* W_hh = (const float*)d_in[8];
    const float* b_hh = (const float*)d_in[9];
    const float* W_out = (const float*)d_in[10];
    const float* b_out = (const float*)d_in[11];
    const float* W_addr = (const float*)d_in[12];
    const float* b_addr = (const float*)d_in[13];
    const float* W_ea = (const float*)d_in[14];
    const float* b_ea = (const float*)d_in[15];
    float* out = (float*)d_out;
    (void)in_sizes; (void)n_in; (void)out_size;

    float *p_xcat, *p_wcat, *p_bcat, *p_gates, *p_c, *p_P, *p_EA, *p_state, *p_outtmp, *p_mem;
    cudaGetSymbolAddress((void**)&p_xcat, g_xcat);
    cudaGetSymbolAddress((void**)&p_wcat, g_wcat);
    cudaGetSymbolAddress((void**)&p_bcat, g_bcat);
    cudaGetSymbolAddress((void**)&p_gates, g_gates);
    cudaGetSymbolAddress((void**)&p_c, g_c);
    cudaGetSymbolAddress((void**)&p_P, g_P);
    cudaGetSymbolAddress((void**)&p_EA, g_EA);
    cudaGetSymbolAddress((void**)&p_state, g_state);
    cudaGetSymbolAddress((void**)&p_outtmp, g_outtmp);
    cudaGetSymbolAddress((void**)&p_mem, g_mem);

    // controller
    k_build_wcat<<<(2048 * 832 + 255) / 256, 256>>>(W_ih, W_hh, b_ih, b_hh);
    k_build_xcat<<<(B_ * 832 + 255) / 256, 256>>>(in_data, prev_reads, h0);
    k_sgemm<<<dim3(32, 4), 256>>>(p_xcat, p_wcat, p_bcat, p_gates, 256, 2048, 832);
    k_lstm<<<(B_ * C_ + 255) / 256, 256>>>(c0);
    k_zero_reads<<<(B_ * 256 + 255) / 256, 256>>>();

    // per-head parameters (head 7 is dead: its write is never observed)
    k_sgemm<<<dim3(9, 4), 256>>>(p_c, W_addr, b_addr, p_P, 256, 560, 512);
    k_sgemm<<<dim3(8, 4), 256>>>(p_c, W_ea, b_ea, p_EA, 256, 512, 512);
    k_params<<<256, 64>>>();

    // pass 0: dots for heads 0,1 + norms over mem0 (input)
    k_pass<false, false, 2><<<dim3(N_ / PASS_ROWS, B_), 256>>>(memory, 0, 0, 0, 0, 0, 1);
    k_weight<<<dim3(B_, 2), 512>>>(prev_weights, 0);
    // pass 1: read h0 (mem0), write h1 -> mem1, dots for heads 2,3 + norms(mem1)
    k_pass<true, true, 2><<<dim3(N_ / PASS_ROWS, B_), 256>>>(memory, 0, 0, 1, 0, 2, 3);
    k_weight<<<dim3(B_, 2), 512>>>(prev_weights, 2);
    // pass 2: read h2 (mem1), write h3 -> mem2, dots for heads 4,5
    k_pass<true, true, 2><<<dim3(N_ / PASS_ROWS, B_), 256>>>(p_mem, 2, 1, 3, 1, 4, 5);
    k_weight<<<dim3(B_, 2), 512>>>(prev_weights, 4);
    // pass 3: read h4 (mem2), write h5 -> mem3, dot for head 6
    k_pass<true, true, 1><<<dim3(N_ / PASS_ROWS, B_), 256>>>(p_mem, 4, 2, 5, 2, 6, 0);
    k_weight<<<dim3(B_, 1), 512>>>(prev_weights, 6);
    // pass 4: read h6 (mem3) only — head 7's write is dead
    k_pass<true, false, 0><<<dim3(N_ / PASS_ROWS, B_), 256>>>(p_mem, 6, 3, 0, 0, 0, 0);

    // output layer
    k_sgemm<<<dim3(1, 4), 256>>>(p_state, W_out, b_out, p_outtmp, 256, 64, 768);
    k_sig_out<<<(B_ * 64 + 255) / 256, 256>>>(out);
}